// round 11
// baseline (speedup 1.0000x reference)
#include <cuda_runtime.h>
#include <cuda_bf16.h>

#define N_NODES 50000
#define N_EDGES 640000
#define NELEM (N_NODES * 128)
#define NBLK 196

// ---------------- scratch (device globals) ----------------
__device__ __align__(16) __nv_bfloat16 g_xhi[NELEM], g_xlo[NELEM];
__device__ __align__(16) __nv_bfloat16 g_thi[NELEM], g_tlo[NELEM];
__device__ __align__(16) __nv_bfloat16 g_zhi[NELEM], g_zlo[NELEM];
__device__ __align__(16) __nv_bfloat16 g_hhi[3][NELEM], g_hlo[3][NELEM];
__device__ __align__(16) __nv_bfloat16 g_wthi[6][128 * 128], g_wtlo[6][128 * 128];
__device__ __align__(16) __nv_bfloat16 g_fwthi[128 * 512], g_fwtlo[128 * 512];
__device__ int g_rowptr[N_NODES + 1], g_cnt[N_NODES], g_cnt2[N_NODES], g_srcs[N_EDGES];
__device__ int g_is64;
__device__ int g_part[256], g_incl[256];
__device__ volatile int g_flag[256];

#define SEL_X 0
#define SEL_T 1
#define SEL_Z 2
#define SEL_H0 3
#define SEL_H1 4
#define SEL_H2 5

__device__ __forceinline__ void sel_hl(int s, const __nv_bfloat16*& hi,
                                       const __nv_bfloat16*& lo) {
    switch (s) {
        case SEL_X: hi = g_xhi; lo = g_xlo; break;
        case SEL_T: hi = g_thi; lo = g_tlo; break;
        case SEL_Z: hi = g_zhi; lo = g_zlo; break;
        case SEL_H0: hi = g_hhi[0]; lo = g_hlo[0]; break;
        case SEL_H1: hi = g_hhi[1]; lo = g_hlo[1]; break;
        default:     hi = g_hhi[2]; lo = g_hlo[2]; break;
    }
}
__device__ __forceinline__ void sel_out(int s, __nv_bfloat16*& hi, __nv_bfloat16*& lo) {
    switch (s) {
        case SEL_T: hi = g_thi; lo = g_tlo; break;
        case SEL_Z: hi = g_zhi; lo = g_zlo; break;
        case SEL_H0: hi = g_hhi[0]; lo = g_hlo[0]; break;
        case SEL_H1: hi = g_hhi[1]; lo = g_hlo[1]; break;
        default:     hi = g_hhi[2]; lo = g_hlo[2]; break;
    }
}

// ---------------- fused prep: zero cnt/cnt2/flags + detect + split x + W ----
__global__ void prep_kernel(const float* __restrict__ x, const int* __restrict__ ei32,
                            const float* __restrict__ W1, const float* __restrict__ W2,
                            const float* __restrict__ fw) {
    int i = blockIdx.x * 256 + threadIdx.x;
    if (i < N_NODES) { g_cnt[i] = 0; g_cnt2[i] = 0; }
    if (i < 256) g_flag[i] = 0;
    if (i == 0) {
        int ornz = 0;
#pragma unroll
        for (int k = 0; k < 64; k++) ornz |= ei32[2 * k + 1];
        g_is64 = (ornz == 0) ? 1 : 0;
    }
    // weight transpose + split
    if (i < 6 * 16384) {
        int m = i >> 14, t = i & 16383;
        int n = t >> 7, k = t & 127;
        int l = m >> 1;
        const float* src = (m & 1) ? W2 : W1;
        float v = src[l * 16384 + k * 128 + n];
        __nv_bfloat16 h = __float2bfloat16_rn(v);
        g_wthi[m][n * 128 + k] = h;
        g_wtlo[m][n * 128 + k] = __float2bfloat16_rn(v - __bfloat162float(h));
    } else if (i < 6 * 16384 + 128 * 512) {
        int t = i - 6 * 16384;
        int n = t >> 9, k = t & 511;
        float v = fw[k * 128 + n];
        __nv_bfloat16 h = __float2bfloat16_rn(v);
        g_fwthi[n * 512 + k] = h;
        g_fwtlo[n * 512 + k] = __float2bfloat16_rn(v - __bfloat162float(h));
    }
    // x split (8 floats per thread)
    if (i < NELEM / 8) {
        const float4* xp = (const float4*)x;
        float4 v0 = xp[2 * i], v1 = xp[2 * i + 1];
        float v[8] = {v0.x, v0.y, v0.z, v0.w, v1.x, v1.y, v1.z, v1.w};
        uint4 hp, lp;
        __nv_bfloat162* h2 = (__nv_bfloat162*)&hp;
        __nv_bfloat162* l2 = (__nv_bfloat162*)&lp;
#pragma unroll
        for (int j = 0; j < 4; j++) {
            __nv_bfloat16 h0 = __float2bfloat16_rn(v[2 * j]);
            __nv_bfloat16 h1 = __float2bfloat16_rn(v[2 * j + 1]);
            h2[j].x = h0; h2[j].y = h1;
            l2[j].x = __float2bfloat16_rn(v[2 * j] - __bfloat162float(h0));
            l2[j].y = __float2bfloat16_rn(v[2 * j + 1] - __bfloat162float(h1));
        }
        ((uint4*)g_xhi)[i] = hp;
        ((uint4*)g_xlo)[i] = lp;
    }
}

// ---------------- CSR build ----------------
__global__ void hist_kernel(const int* __restrict__ ei32) {
    int e = (blockIdx.x * 256 + threadIdx.x) * 4;
    if (e >= N_EDGES) return;
    int is64 = g_is64;
    int d0, d1, d2, d3;
    if (is64) {
        int4 a = *(const int4*)&ei32[2 * (N_EDGES + e)];
        int4 b = *(const int4*)&ei32[2 * (N_EDGES + e) + 4];
        d0 = a.x; d1 = a.z; d2 = b.x; d3 = b.z;
    } else {
        int4 a = *(const int4*)&ei32[N_EDGES + e];
        d0 = a.x; d1 = a.y; d2 = a.z; d3 = a.w;
    }
    if ((unsigned)d0 < (unsigned)N_NODES) atomicAdd(&g_cnt[d0], 1);
    if ((unsigned)d1 < (unsigned)N_NODES) atomicAdd(&g_cnt[d1], 1);
    if ((unsigned)d2 < (unsigned)N_NODES) atomicAdd(&g_cnt[d2], 1);
    if ((unsigned)d3 < (unsigned)N_NODES) atomicAdd(&g_cnt[d3], 1);
}

// single-pass decoupled-lookback scan -> g_rowptr
__global__ void scan_kernel() {
    __shared__ int sh[256];
    __shared__ int s_excl;
    const int t = threadIdx.x, b = blockIdx.x;
    const int i = b * 256 + t;
    int v = (i < N_NODES) ? g_cnt[i] : 0;
    sh[t] = v;
    __syncthreads();
#pragma unroll
    for (int off = 1; off < 256; off <<= 1) {
        int a = (t >= off) ? sh[t - off] : 0;
        __syncthreads();
        sh[t] += a;
        __syncthreads();
    }
    const int total = sh[255];

    // publish partial
    if (t == 0 && b > 0) {
        g_part[b] = total;
        __threadfence();
        g_flag[b] = 1;
    }

    // warp 0: lookback to compute exclusive prefix of block b
    if (t < 32) {
        int excl = 0;
        if (b > 0) {
            int look = b - 1;
            for (;;) {
                int idx = look - t;
                int f = 0;
                if (idx >= 0) {
                    while ((f = g_flag[idx]) == 0) {}
                    __threadfence();
                }
                unsigned incl_mask = __ballot_sync(0xffffffffu, idx >= 0 && f == 2);
                int contrib = 0;
                if (incl_mask) {
                    int lead = __ffs(incl_mask) - 1;   // nearest INCLUSIVE predecessor
                    if (t < lead) contrib = g_part[idx];
                    else if (t == lead) contrib = g_incl[idx];
                } else {
                    contrib = (idx >= 0) ? g_part[idx] : 0;
                }
#pragma unroll
                for (int off = 16; off > 0; off >>= 1)
                    contrib += __shfl_down_sync(0xffffffffu, contrib, off);
                if (t == 0) excl += contrib;
                if (incl_mask) break;
                look -= 32;
                if (look < 0) break;
            }
        }
        if (t == 0) {
            s_excl = excl;
            g_incl[b] = excl + total;
            __threadfence();
            g_flag[b] = 2;
        }
    }
    __syncthreads();
    const int excl = s_excl;
    if (i < N_NODES) g_rowptr[i] = excl + sh[t] - v;
    if (b == NBLK - 1 && t == 255) g_rowptr[N_NODES] = excl + total;
}

__global__ void scatter_kernel(const int* __restrict__ ei32) {
    int e = (blockIdx.x * 256 + threadIdx.x) * 4;
    if (e >= N_EDGES) return;
    int is64 = g_is64;
    int s0, s1, s2, s3, d0, d1, d2, d3;
    if (is64) {
        int4 a = *(const int4*)&ei32[2 * e];
        int4 b = *(const int4*)&ei32[2 * e + 4];
        s0 = a.x; s1 = a.z; s2 = b.x; s3 = b.z;
        int4 c = *(const int4*)&ei32[2 * (N_EDGES + e)];
        int4 d = *(const int4*)&ei32[2 * (N_EDGES + e) + 4];
        d0 = c.x; d1 = c.z; d2 = d.x; d3 = d.z;
    } else {
        int4 a = *(const int4*)&ei32[e];
        s0 = a.x; s1 = a.y; s2 = a.z; s3 = a.w;
        int4 c = *(const int4*)&ei32[N_EDGES + e];
        d0 = c.x; d1 = c.y; d2 = c.z; d3 = c.w;
    }
#define SCAT1(ss, dd) \
    if ((unsigned)(dd) < (unsigned)N_NODES && (unsigned)(ss) < (unsigned)N_NODES) { \
        int pos = g_rowptr[dd] + atomicAdd(&g_cnt2[dd], 1); \
        if ((unsigned)pos < (unsigned)N_EDGES) g_srcs[pos] = (ss); \
    }
    SCAT1(s0, d0) SCAT1(s1, d1) SCAT1(s2, d2) SCAT1(s3, d3)
#undef SCAT1
}

// ---------------- aggregation: t = (1+eps)*h + segsum (hi/lo pairs) ---------
__global__ void agg_kernel(int hsel, const float* __restrict__ eps, int l) {
    const __nv_bfloat16 *hib, *lob;
    sel_hl(hsel, hib, lob);
    int wnode = (blockIdx.x * blockDim.x + threadIdx.x) >> 5;
    int lane = threadIdx.x & 31;
    if (wnode >= N_NODES) return;
    int half = lane >> 4;
    int p = lane & 15;
    const uint4* rows = (const uint4*)(half ? lob : hib);
    float acc[8];
#pragma unroll
    for (int j = 0; j < 8; j++) acc[j] = 0.f;

    int beg = g_rowptr[wnode], end = g_rowptr[wnode + 1];
    int i = beg;
    for (; i + 4 <= end; i += 4) {
        int s0 = g_srcs[i], s1 = g_srcs[i + 1];
        int s2 = g_srcs[i + 2], s3 = g_srcs[i + 3];
        uint4 v0 = rows[s0 * 16 + p];
        uint4 v1 = rows[s1 * 16 + p];
        uint4 v2 = rows[s2 * 16 + p];
        uint4 v3 = rows[s3 * 16 + p];
        const __nv_bfloat162* p0 = (const __nv_bfloat162*)&v0;
        const __nv_bfloat162* p1 = (const __nv_bfloat162*)&v1;
        const __nv_bfloat162* p2 = (const __nv_bfloat162*)&v2;
        const __nv_bfloat162* p3 = (const __nv_bfloat162*)&v3;
#pragma unroll
        for (int j = 0; j < 4; j++) {
            float2 f0 = __bfloat1622float2(p0[j]);
            float2 f1 = __bfloat1622float2(p1[j]);
            float2 f2 = __bfloat1622float2(p2[j]);
            float2 f3 = __bfloat1622float2(p3[j]);
            acc[2 * j]     += (f0.x + f1.x) + (f2.x + f3.x);
            acc[2 * j + 1] += (f0.y + f1.y) + (f2.y + f3.y);
        }
    }
    for (; i < end; i++) {
        uint4 v = rows[g_srcs[i] * 16 + p];
        const __nv_bfloat162* pv = (const __nv_bfloat162*)&v;
#pragma unroll
        for (int j = 0; j < 4; j++) {
            float2 f = __bfloat1622float2(pv[j]);
            acc[2 * j] += f.x;
            acc[2 * j + 1] += f.y;
        }
    }
    float e = 1.0f + eps[l];
    {
        uint4 v = rows[wnode * 16 + p];
        const __nv_bfloat162* pv = (const __nv_bfloat162*)&v;
#pragma unroll
        for (int j = 0; j < 4; j++) {
            float2 f = __bfloat1622float2(pv[j]);
            acc[2 * j] += e * f.x;
            acc[2 * j + 1] += e * f.y;
        }
    }
    float tot[8];
#pragma unroll
    for (int j = 0; j < 8; j++)
        tot[j] = acc[j] + __shfl_xor_sync(0xffffffffu, acc[j], 16);
    uint4 outv;
    __nv_bfloat162* o2 = (__nv_bfloat162*)&outv;
#pragma unroll
    for (int j = 0; j < 4; j++) {
        __nv_bfloat16 h0 = __float2bfloat16_rn(tot[2 * j]);
        __nv_bfloat16 h1 = __float2bfloat16_rn(tot[2 * j + 1]);
        if (half == 0) { o2[j].x = h0; o2[j].y = h1; }
        else {
            o2[j].x = __float2bfloat16_rn(tot[2 * j] - __bfloat162float(h0));
            o2[j].y = __float2bfloat16_rn(tot[2 * j + 1] - __bfloat162float(h1));
        }
    }
    uint4* dst = (uint4*)(half ? g_tlo : g_thi);
    dst[wnode * 16 + p] = outv;
}

// ---------------- tensor-core GEMM machinery ----------------
__device__ __forceinline__ void cp16(unsigned s, const void* g, bool pred) {
    int sz = pred ? 16 : 0;
    asm volatile("cp.async.cg.shared.global [%0], [%1], 16, %2;\n"
                 :: "r"(s), "l"(g), "r"(sz));
}
__device__ __forceinline__ void cp_commit() { asm volatile("cp.async.commit_group;\n"); }
template <int N>
__device__ __forceinline__ void cp_wait() {
    asm volatile("cp.async.wait_group %0;\n" :: "n"(N) : "memory");
}

__device__ __forceinline__ void ldsm4(unsigned* r, unsigned addr) {
    asm volatile("ldmatrix.sync.aligned.m8n8.x4.shared.b16 {%0,%1,%2,%3}, [%4];"
                 : "=r"(r[0]), "=r"(r[1]), "=r"(r[2]), "=r"(r[3]) : "r"(addr));
}
__device__ __forceinline__ void mma_bf16(float* c, const unsigned* a, const unsigned* b) {
    asm volatile(
        "mma.sync.aligned.m16n8k16.row.col.f32.bf16.bf16.f32 "
        "{%0,%1,%2,%3},{%4,%5,%6,%7},{%8,%9},{%0,%1,%2,%3};"
        : "+f"(c[0]), "+f"(c[1]), "+f"(c[2]), "+f"(c[3])
        : "r"(a[0]), "r"(a[1]), "r"(a[2]), "r"(a[3]), "r"(b[0]), "r"(b[1]));
}
__device__ __forceinline__ void store_hl(__nv_bfloat16* Ohi, __nv_bfloat16* Olo,
                                         long long off, float v0, float v1) {
    __nv_bfloat16 h0 = __float2bfloat16_rn(v0), h1 = __float2bfloat16_rn(v1);
    __nv_bfloat162 hp; hp.x = h0; hp.y = h1;
    *(__nv_bfloat162*)(Ohi + off) = hp;
    __nv_bfloat162 lp;
    lp.x = __float2bfloat16_rn(v0 - __bfloat162float(h0));
    lp.y = __float2bfloat16_rn(v1 - __bfloat162float(h1));
    *(__nv_bfloat162*)(Olo + off) = lp;
}

// 4-stage dynamic smem: per stage mats {Ahi, Alo, Whi, Wlo}, each 128 rows x 24 bf16
#define MAT_BYTES 6144u
#define NSTAGE 4
#define SMEM_BYTES (NSTAGE * 4 * MAT_BYTES)   // 98304

__device__ __forceinline__ void mma_chunk(unsigned mbase, int aoff0, int aoff1,
                                          const int* woff, float acc[2][8][4]) {
    unsigned ah[2][4], al[2][4];
    ldsm4(ah[0], mbase + 0 * MAT_BYTES + aoff0);
    ldsm4(ah[1], mbase + 0 * MAT_BYTES + aoff1);
    ldsm4(al[0], mbase + 1 * MAT_BYTES + aoff0);
    ldsm4(al[1], mbase + 1 * MAT_BYTES + aoff1);
#pragma unroll
    for (int ng = 0; ng < 4; ng++) {
        unsigned bh[4], bl[4];
        ldsm4(bh, mbase + 2 * MAT_BYTES + woff[ng]);
        ldsm4(bl, mbase + 3 * MAT_BYTES + woff[ng]);
#pragma unroll
        for (int mi = 0; mi < 2; mi++)
#pragma unroll
            for (int ns = 0; ns < 2; ns++) {
                float* C = acc[mi][ng * 2 + ns];
                mma_bf16(C, ah[mi], &bh[ns * 2]);
                mma_bf16(C, ah[mi], &bl[ns * 2]);
                mma_bf16(C, al[mi], &bh[ns * 2]);
            }
    }
}

// ---------------- layer GEMM: out = relu(A @ W + bias), K=128, BM=128 --------
__global__ void __launch_bounds__(256, 2)
mma_gemm_kernel(int a_sel, int w_idx, const float* __restrict__ bias, int o_sel) {
    extern __shared__ __nv_bfloat16 dynsm[];
    const unsigned base = (unsigned)__cvta_generic_to_shared(dynsm);

    const __nv_bfloat16 *Ahi, *Alo;
    sel_hl(a_sel, Ahi, Alo);
    __nv_bfloat16 *Ohi, *Olo;
    sel_out(o_sel, Ohi, Olo);
    const __nv_bfloat16* Whi = g_wthi[w_idx];
    const __nv_bfloat16* Wlo = g_wtlo[w_idx];

    const int tid = threadIdx.x, lane = tid & 31, w = tid >> 5;
    const int wm = w & 3, wn = w >> 2;
    const int rowBase = blockIdx.x * 128;
    const int g = lane >> 3, r = lane & 7;

    const int aoff0 = (wm * 32 + 0 + (g & 1) * 8 + r) * 48 + (g >> 1) * 16;
    const int aoff1 = (wm * 32 + 16 + (g & 1) * 8 + r) * 48 + (g >> 1) * 16;
    int woff[4];
#pragma unroll
    for (int ng = 0; ng < 4; ng++)
        woff[ng] = (wn * 64 + ng * 16 + (g >> 1) * 8 + r) * 48 + (g & 1) * 16;

    float acc[2][8][4];
#pragma unroll
    for (int i = 0; i < 2; i++)
#pragma unroll
        for (int j = 0; j < 8; j++)
#pragma unroll
            for (int q = 0; q < 4; q++) acc[i][j][q] = 0.f;

    const int crow = tid >> 1, chalf = tid & 1;
    const unsigned dsto = (unsigned)(crow * 48 + chalf * 16);
    const bool aok = (rowBase + crow) < N_NODES;
    const long long arow = (long long)(rowBase + crow) * 128;

#pragma unroll
    for (int pc = 0; pc < 3; pc++) {
        unsigned mb = base + (unsigned)pc * 4 * MAT_BYTES;
        int kb = pc * 16 + chalf * 8;
        cp16(mb + 0 * MAT_BYTES + dsto, Ahi + arow + kb, aok);
        cp16(mb + 1 * MAT_BYTES + dsto, Alo + arow + kb, aok);
        cp16(mb + 2 * MAT_BYTES + dsto, Whi + crow * 128 + kb, true);
        cp16(mb + 3 * MAT_BYTES + dsto, Wlo + crow * 128 + kb, true);
        cp_commit();
    }

#pragma unroll
    for (int c = 0; c < 8; c++) {
        if (c < 6) cp_wait<2>();
        else if (c == 6) cp_wait<1>();
        else cp_wait<0>();
        __syncthreads();
        mma_chunk(base + (unsigned)(c & 3) * 4 * MAT_BYTES, aoff0, aoff1, woff, acc);
        if (c + 3 < 8) {
            unsigned mb = base + (unsigned)((c + 3) & 3) * 4 * MAT_BYTES;
            int kb = (c + 3) * 16 + chalf * 8;
            cp16(mb + 0 * MAT_BYTES + dsto, Ahi + arow + kb, aok);
            cp16(mb + 1 * MAT_BYTES + dsto, Alo + arow + kb, aok);
            cp16(mb + 2 * MAT_BYTES + dsto, Whi + crow * 128 + kb, true);
            cp16(mb + 3 * MAT_BYTES + dsto, Wlo + crow * 128 + kb, true);
            cp_commit();
        }
    }

#pragma unroll
    for (int ni = 0; ni < 8; ni++) {
        int n0 = wn * 64 + ni * 8 + 2 * (lane & 3);
        float2 bv = *(const float2*)&bias[n0];
#pragma unroll
        for (int mi = 0; mi < 2; mi++) {
            int r0 = rowBase + wm * 32 + mi * 16 + (lane >> 2);
            float* C = acc[mi][ni];
            float v0 = fmaxf(C[0] + bv.x, 0.f), v1 = fmaxf(C[1] + bv.y, 0.f);
            float v2 = fmaxf(C[2] + bv.x, 0.f), v3 = fmaxf(C[3] + bv.y, 0.f);
            if (r0 < N_NODES) store_hl(Ohi, Olo, (long long)r0 * 128 + n0, v0, v1);
            if (r0 + 8 < N_NODES) store_hl(Ohi, Olo, (long long)(r0 + 8) * 128 + n0, v2, v3);
        }
    }
}

// ---------------- final GEMM: out = concat(x,h0,h1,h2) @ fw + fb, K=512 ------
__device__ __forceinline__ void final_src(int s, const __nv_bfloat16*& hi,
                                          const __nv_bfloat16*& lo) {
    switch (s) {
        case 0: hi = g_xhi; lo = g_xlo; break;
        case 1: hi = g_hhi[0]; lo = g_hlo[0]; break;
        case 2: hi = g_hhi[1]; lo = g_hlo[1]; break;
        default: hi = g_hhi[2]; lo = g_hlo[2]; break;
    }
}

__global__ void __launch_bounds__(256, 2)
final_gemm_kernel(const float* __restrict__ fb, float* __restrict__ out) {
    extern __shared__ __nv_bfloat16 dynsm[];
    const unsigned base = (unsigned)__cvta_generic_to_shared(dynsm);

    const int tid = threadIdx.x, lane = tid & 31, w = tid >> 5;
    const int wm = w & 3, wn = w >> 2;
    const int rowBase = blockIdx.x * 128;
    const int g = lane >> 3, r = lane & 7;

    const int aoff0 = (wm * 32 + 0 + (g & 1) * 8 + r) * 48 + (g >> 1) * 16;
    const int aoff1 = (wm * 32 + 16 + (g & 1) * 8 + r) * 48 + (g >> 1) * 16;
    int woff[4];
#pragma unroll
    for (int ng = 0; ng < 4; ng++)
        woff[ng] = (wn * 64 + ng * 16 + (g >> 1) * 8 + r) * 48 + (g & 1) * 16;

    float acc[2][8][4];
#pragma unroll
    for (int i = 0; i < 2; i++)
#pragma unroll
        for (int j = 0; j < 8; j++)
#pragma unroll
            for (int q = 0; q < 4; q++) acc[i][j][q] = 0.f;

    const int crow = tid >> 1, chalf = tid & 1;
    const unsigned dsto = (unsigned)(crow * 48 + chalf * 16);
    const bool aok = (rowBase + crow) < N_NODES;
    const long long arow = (long long)(rowBase + crow) * 128;

#pragma unroll
    for (int pc = 0; pc < 3; pc++) {
        const __nv_bfloat16 *shi, *slo;
        final_src(pc >> 3, shi, slo);
        unsigned mb = base + (unsigned)pc * 4 * MAT_BYTES;
        int ka = (pc & 7) * 16 + chalf * 8;
        int kw = pc * 16 + chalf * 8;
        cp16(mb + 0 * MAT_BYTES + dsto, shi + arow + ka, aok);
        cp16(mb + 1 * MAT_BYTES + dsto, slo + arow + ka, aok);
        cp16(mb + 2 * MAT_BYTES + dsto, g_fwthi + crow * 512 + kw, true);
        cp16(mb + 3 * MAT_BYTES + dsto, g_fwtlo + crow * 512 + kw, true);
        cp_commit();
    }

    for (int c = 0; c < 32; c++) {
        if (c < 30) cp_wait<2>();
        else if (c == 30) cp_wait<1>();
        else cp_wait<0>();
        __syncthreads();
        mma_chunk(base + (unsigned)(c & 3) * 4 * MAT_BYTES, aoff0, aoff1, woff, acc);
        if (c + 3 < 32) {
            int cn = c + 3;
            const __nv_bfloat16 *shi, *slo;
            final_src(cn >> 3, shi, slo);
            unsigned mb = base + (unsigned)(cn & 3) * 4 * MAT_BYTES;
            int ka = (cn & 7) * 16 + chalf * 8;
            int kw = cn * 16 + chalf * 8;
            cp16(mb + 0 * MAT_BYTES + dsto, shi + arow + ka, aok);
            cp16(mb + 1 * MAT_BYTES + dsto, slo + arow + ka, aok);
            cp16(mb + 2 * MAT_BYTES + dsto, g_fwthi + crow * 512 + kw, true);
            cp16(mb + 3 * MAT_BYTES + dsto, g_fwtlo + crow * 512 + kw, true);
            cp_commit();
        }
    }

#pragma unroll
    for (int ni = 0; ni < 8; ni++) {
        int n0 = wn * 64 + ni * 8 + 2 * (lane & 3);
        float2 bv = *(const float2*)&fb[n0];
#pragma unroll
        for (int mi = 0; mi < 2; mi++) {
            int r0 = rowBase + wm * 32 + mi * 16 + (lane >> 2);
            float* C = acc[mi][ni];
            if (r0 < N_NODES) {
                float2 o = make_float2(C[0] + bv.x, C[1] + bv.y);
                *(float2*)&out[(long long)r0 * 128 + n0] = o;
            }
            if (r0 + 8 < N_NODES) {
                float2 o = make_float2(C[2] + bv.x, C[3] + bv.y);
                *(float2*)&out[(long long)(r0 + 8) * 128 + n0] = o;
            }
        }
    }
}

// ---------------- launch ----------------
extern "C" void kernel_launch(void* const* d_in, const int* in_sizes, int n_in,
                              void* d_out, int out_size) {
    const float* x   = (const float*)d_in[0];
    const int*   ei  = (const int*)d_in[1];
    const float* W1  = (const float*)d_in[2];
    const float* b1  = (const float*)d_in[3];
    const float* W2  = (const float*)d_in[4];
    const float* b2  = (const float*)d_in[5];
    const float* eps = (const float*)d_in[6];
    const float* fw  = (const float*)d_in[7];
    const float* fb  = (const float*)d_in[8];
    float* out = (float*)d_out;

    cudaFuncSetAttribute(mma_gemm_kernel,
                         cudaFuncAttributeMaxDynamicSharedMemorySize, SMEM_BYTES);
    cudaFuncSetAttribute(final_gemm_kernel,
                         cudaFuncAttributeMaxDynamicSharedMemorySize, SMEM_BYTES);

    const int PB = (NELEM / 8 + 255) / 256;          // 3125 (covers all prep work)
    const int EB4 = (N_EDGES / 4 + 255) / 256;       // 625
    const int GB = (N_NODES + 127) / 128;            // 391
    const int AB = (N_NODES * 32 + 255) / 256;       // warp per node

    // fused prep + single-pass CSR build
    prep_kernel<<<PB, 256>>>(x, ei, W1, W2, fw);
    hist_kernel<<<EB4, 256>>>(ei);
    scan_kernel<<<NBLK, 256>>>();
    scatter_kernel<<<EB4, 256>>>(ei);

    // 3 GIN layers
    int hin[3]  = { SEL_X, SEL_H0, SEL_H1 };
    int hout[3] = { SEL_H0, SEL_H1, SEL_H2 };
    for (int l = 0; l < 3; l++) {
        agg_kernel<<<AB, 256>>>(hin[l], eps, l);
        mma_gemm_kernel<<<GB, 256, SMEM_BYTES>>>(SEL_T, 2 * l,     b1 + l * 128, SEL_Z);
        mma_gemm_kernel<<<GB, 256, SMEM_BYTES>>>(SEL_Z, 2 * l + 1, b2 + l * 128, hout[l]);
    }
    final_gemm_kernel<<<GB, 256, SMEM_BYTES>>>(fb, out);
}

// round 12
// speedup vs baseline: 1.0229x; 1.0229x over previous
#include <cuda_runtime.h>
#include <cuda_bf16.h>

#define N_NODES 50000
#define N_EDGES 640000
#define NELEM (N_NODES * 128)
#define NBLK 196

// ---------------- scratch (device globals) ----------------
__device__ __align__(16) __nv_bfloat16 g_xhi[NELEM], g_xlo[NELEM];
__device__ __align__(16) __nv_bfloat16 g_thi[NELEM], g_tlo[NELEM];
__device__ __align__(16) __nv_bfloat16 g_zhi[NELEM], g_zlo[NELEM];
__device__ __align__(16) __nv_bfloat16 g_hhi[3][NELEM], g_hlo[3][NELEM];
__device__ __align__(16) __nv_bfloat16 g_wthi[6][128 * 128], g_wtlo[6][128 * 128];
__device__ __align__(16) __nv_bfloat16 g_fwthi[128 * 512], g_fwtlo[128 * 512];
__device__ int g_rowptr[N_NODES + 1], g_cnt[N_NODES], g_cnt2[N_NODES], g_srcs[N_EDGES];
__device__ int g_is64, g_bsum[256];

#define SEL_X 0
#define SEL_T 1
#define SEL_Z 2
#define SEL_H0 3
#define SEL_H1 4
#define SEL_H2 5

__device__ __forceinline__ void sel_hl(int s, const __nv_bfloat16*& hi,
                                       const __nv_bfloat16*& lo) {
    switch (s) {
        case SEL_X: hi = g_xhi; lo = g_xlo; break;
        case SEL_T: hi = g_thi; lo = g_tlo; break;
        case SEL_Z: hi = g_zhi; lo = g_zlo; break;
        case SEL_H0: hi = g_hhi[0]; lo = g_hlo[0]; break;
        case SEL_H1: hi = g_hhi[1]; lo = g_hlo[1]; break;
        default:     hi = g_hhi[2]; lo = g_hlo[2]; break;
    }
}
__device__ __forceinline__ void sel_out(int s, __nv_bfloat16*& hi, __nv_bfloat16*& lo) {
    switch (s) {
        case SEL_T: hi = g_thi; lo = g_tlo; break;
        case SEL_Z: hi = g_zhi; lo = g_zlo; break;
        case SEL_H0: hi = g_hhi[0]; lo = g_hlo[0]; break;
        case SEL_H1: hi = g_hhi[1]; lo = g_hlo[1]; break;
        default:     hi = g_hhi[2]; lo = g_hlo[2]; break;
    }
}

// ---------------- fused prep: zero cnt + detect dtype + split x + split W ----
__global__ void prep_kernel(const float* __restrict__ x, const int* __restrict__ ei32,
                            const float* __restrict__ W1, const float* __restrict__ W2,
                            const float* __restrict__ fw) {
    int i = blockIdx.x * 256 + threadIdx.x;
    if (i < N_NODES) g_cnt[i] = 0;
    if (i == 0) {
        int ornz = 0;
#pragma unroll
        for (int k = 0; k < 64; k++) ornz |= ei32[2 * k + 1];
        g_is64 = (ornz == 0) ? 1 : 0;
    }
    // weight transpose + split
    if (i < 6 * 16384) {
        int m = i >> 14, t = i & 16383;
        int n = t >> 7, k = t & 127;
        int l = m >> 1;
        const float* src = (m & 1) ? W2 : W1;
        float v = src[l * 16384 + k * 128 + n];
        __nv_bfloat16 h = __float2bfloat16_rn(v);
        g_wthi[m][n * 128 + k] = h;
        g_wtlo[m][n * 128 + k] = __float2bfloat16_rn(v - __bfloat162float(h));
    } else if (i < 6 * 16384 + 128 * 512) {
        int t = i - 6 * 16384;
        int n = t >> 9, k = t & 511;
        float v = fw[k * 128 + n];
        __nv_bfloat16 h = __float2bfloat16_rn(v);
        g_fwthi[n * 512 + k] = h;
        g_fwtlo[n * 512 + k] = __float2bfloat16_rn(v - __bfloat162float(h));
    }
    // x split (8 floats per thread)
    if (i < NELEM / 8) {
        const float4* xp = (const float4*)x;
        float4 v0 = xp[2 * i], v1 = xp[2 * i + 1];
        float v[8] = {v0.x, v0.y, v0.z, v0.w, v1.x, v1.y, v1.z, v1.w};
        uint4 hp, lp;
        __nv_bfloat162* h2 = (__nv_bfloat162*)&hp;
        __nv_bfloat162* l2 = (__nv_bfloat162*)&lp;
#pragma unroll
        for (int j = 0; j < 4; j++) {
            __nv_bfloat16 h0 = __float2bfloat16_rn(v[2 * j]);
            __nv_bfloat16 h1 = __float2bfloat16_rn(v[2 * j + 1]);
            h2[j].x = h0; h2[j].y = h1;
            l2[j].x = __float2bfloat16_rn(v[2 * j] - __bfloat162float(h0));
            l2[j].y = __float2bfloat16_rn(v[2 * j + 1] - __bfloat162float(h1));
        }
        ((uint4*)g_xhi)[i] = hp;
        ((uint4*)g_xlo)[i] = lp;
    }
}

// ---------------- CSR build ----------------
// 8 edges per thread for deeper MLP on the atomic chains
__global__ void hist_kernel(const int* __restrict__ ei32) {
    int e = (blockIdx.x * 256 + threadIdx.x) * 8;
    if (e >= N_EDGES) return;
    int is64 = g_is64;
    int d[8];
    if (is64) {
#pragma unroll
        for (int q = 0; q < 4; q++) {
            int4 a = *(const int4*)&ei32[2 * (N_EDGES + e) + 4 * q];
            d[2 * q] = a.x; d[2 * q + 1] = a.z;
        }
    } else {
        int4 a = *(const int4*)&ei32[N_EDGES + e];
        int4 b = *(const int4*)&ei32[N_EDGES + e + 4];
        d[0] = a.x; d[1] = a.y; d[2] = a.z; d[3] = a.w;
        d[4] = b.x; d[5] = b.y; d[6] = b.z; d[7] = b.w;
    }
#pragma unroll
    for (int q = 0; q < 8; q++)
        if ((unsigned)d[q] < (unsigned)N_NODES) atomicAdd(&g_cnt[d[q]], 1);
}

__global__ void bsum_kernel() {   // per-block sums; also zeroes g_cnt2
    __shared__ int sh[256];
    int t = threadIdx.x, i = blockIdx.x * 256 + t;
    if (i < N_NODES) g_cnt2[i] = 0;
    sh[t] = (i < N_NODES) ? g_cnt[i] : 0;
    __syncthreads();
#pragma unroll
    for (int off = 128; off > 0; off >>= 1) {
        if (t < off) sh[t] += sh[t + off];
        __syncthreads();
    }
    if (t == 0) g_bsum[blockIdx.x] = sh[0];
}

// rowptr: each block scans the 196 block-sums itself
__global__ void rowptr_kernel() {
    __shared__ int sb[256];
    __shared__ int sh[256];
    int t = threadIdx.x, i = blockIdx.x * 256 + t;
    int bv = (t < NBLK) ? g_bsum[t] : 0;
    sb[t] = bv;
    __syncthreads();
#pragma unroll
    for (int off = 1; off < 256; off <<= 1) {
        int a = (t >= off) ? sb[t - off] : 0;
        __syncthreads();
        sb[t] += a;
        __syncthreads();
    }
    int boff = sb[blockIdx.x] - g_bsum[blockIdx.x];
    if (blockIdx.x == 0 && t == 0) g_rowptr[N_NODES] = sb[255];

    int v = (i < N_NODES) ? g_cnt[i] : 0;
    sh[t] = v;
    __syncthreads();
#pragma unroll
    for (int off = 1; off < 256; off <<= 1) {
        int a = (t >= off) ? sh[t - off] : 0;
        __syncthreads();
        sh[t] += a;
        __syncthreads();
    }
    if (i < N_NODES) g_rowptr[i] = boff + sh[t] - v;
}

__global__ void scatter_kernel(const int* __restrict__ ei32) {
    int e = (blockIdx.x * 256 + threadIdx.x) * 8;
    if (e >= N_EDGES) return;
    int is64 = g_is64;
    int s[8], d[8];
    if (is64) {
#pragma unroll
        for (int q = 0; q < 4; q++) {
            int4 a = *(const int4*)&ei32[2 * e + 4 * q];
            s[2 * q] = a.x; s[2 * q + 1] = a.z;
            int4 c = *(const int4*)&ei32[2 * (N_EDGES + e) + 4 * q];
            d[2 * q] = c.x; d[2 * q + 1] = c.z;
        }
    } else {
        int4 a = *(const int4*)&ei32[e];
        int4 b = *(const int4*)&ei32[e + 4];
        s[0] = a.x; s[1] = a.y; s[2] = a.z; s[3] = a.w;
        s[4] = b.x; s[5] = b.y; s[6] = b.z; s[7] = b.w;
        int4 c = *(const int4*)&ei32[N_EDGES + e];
        int4 f = *(const int4*)&ei32[N_EDGES + e + 4];
        d[0] = c.x; d[1] = c.y; d[2] = c.z; d[3] = c.w;
        d[4] = f.x; d[5] = f.y; d[6] = f.z; d[7] = f.w;
    }
#pragma unroll
    for (int q = 0; q < 8; q++) {
        if ((unsigned)d[q] < (unsigned)N_NODES && (unsigned)s[q] < (unsigned)N_NODES) {
            int pos = g_rowptr[d[q]] + atomicAdd(&g_cnt2[d[q]], 1);
            if ((unsigned)pos < (unsigned)N_EDGES) g_srcs[pos] = s[q];
        }
    }
}

// ---------------- aggregation: t = (1+eps)*h + segsum (hi/lo pairs) ---------
__global__ void agg_kernel(int hsel, const float* __restrict__ eps, int l) {
    const __nv_bfloat16 *hib, *lob;
    sel_hl(hsel, hib, lob);
    int wnode = (blockIdx.x * blockDim.x + threadIdx.x) >> 5;
    int lane = threadIdx.x & 31;
    if (wnode >= N_NODES) return;
    int half = lane >> 4;
    int p = lane & 15;
    const uint4* rows = (const uint4*)(half ? lob : hib);
    float acc[8];
#pragma unroll
    for (int j = 0; j < 8; j++) acc[j] = 0.f;

    int beg = g_rowptr[wnode], end = g_rowptr[wnode + 1];
    int i = beg;
    for (; i + 4 <= end; i += 4) {
        int s0 = g_srcs[i], s1 = g_srcs[i + 1];
        int s2 = g_srcs[i + 2], s3 = g_srcs[i + 3];
        uint4 v0 = rows[s0 * 16 + p];
        uint4 v1 = rows[s1 * 16 + p];
        uint4 v2 = rows[s2 * 16 + p];
        uint4 v3 = rows[s3 * 16 + p];
        const __nv_bfloat162* p0 = (const __nv_bfloat162*)&v0;
        const __nv_bfloat162* p1 = (const __nv_bfloat162*)&v1;
        const __nv_bfloat162* p2 = (const __nv_bfloat162*)&v2;
        const __nv_bfloat162* p3 = (const __nv_bfloat162*)&v3;
#pragma unroll
        for (int j = 0; j < 4; j++) {
            float2 f0 = __bfloat1622float2(p0[j]);
            float2 f1 = __bfloat1622float2(p1[j]);
            float2 f2 = __bfloat1622float2(p2[j]);
            float2 f3 = __bfloat1622float2(p3[j]);
            acc[2 * j]     += (f0.x + f1.x) + (f2.x + f3.x);
            acc[2 * j + 1] += (f0.y + f1.y) + (f2.y + f3.y);
        }
    }
    for (; i < end; i++) {
        uint4 v = rows[g_srcs[i] * 16 + p];
        const __nv_bfloat162* pv = (const __nv_bfloat162*)&v;
#pragma unroll
        for (int j = 0; j < 4; j++) {
            float2 f = __bfloat1622float2(pv[j]);
            acc[2 * j] += f.x;
            acc[2 * j + 1] += f.y;
        }
    }
    float e = 1.0f + eps[l];
    {
        uint4 v = rows[wnode * 16 + p];
        const __nv_bfloat162* pv = (const __nv_bfloat162*)&v;
#pragma unroll
        for (int j = 0; j < 4; j++) {
            float2 f = __bfloat1622float2(pv[j]);
            acc[2 * j] += e * f.x;
            acc[2 * j + 1] += e * f.y;
        }
    }
    float tot[8];
#pragma unroll
    for (int j = 0; j < 8; j++)
        tot[j] = acc[j] + __shfl_xor_sync(0xffffffffu, acc[j], 16);
    uint4 outv;
    __nv_bfloat162* o2 = (__nv_bfloat162*)&outv;
#pragma unroll
    for (int j = 0; j < 4; j++) {
        __nv_bfloat16 h0 = __float2bfloat16_rn(tot[2 * j]);
        __nv_bfloat16 h1 = __float2bfloat16_rn(tot[2 * j + 1]);
        if (half == 0) { o2[j].x = h0; o2[j].y = h1; }
        else {
            o2[j].x = __float2bfloat16_rn(tot[2 * j] - __bfloat162float(h0));
            o2[j].y = __float2bfloat16_rn(tot[2 * j + 1] - __bfloat162float(h1));
        }
    }
    uint4* dst = (uint4*)(half ? g_tlo : g_thi);
    dst[wnode * 16 + p] = outv;
}

// ---------------- tensor-core GEMM machinery ----------------
__device__ __forceinline__ void cp16(unsigned s, const void* g, bool pred) {
    int sz = pred ? 16 : 0;
    asm volatile("cp.async.cg.shared.global [%0], [%1], 16, %2;\n"
                 :: "r"(s), "l"(g), "r"(sz));
}
__device__ __forceinline__ void cp_commit() { asm volatile("cp.async.commit_group;\n"); }
template <int N>
__device__ __forceinline__ void cp_wait() {
    asm volatile("cp.async.wait_group %0;\n" :: "n"(N) : "memory");
}

__device__ __forceinline__ void ldsm4(unsigned* r, unsigned addr) {
    asm volatile("ldmatrix.sync.aligned.m8n8.x4.shared.b16 {%0,%1,%2,%3}, [%4];"
                 : "=r"(r[0]), "=r"(r[1]), "=r"(r[2]), "=r"(r[3]) : "r"(addr));
}
__device__ __forceinline__ void mma_bf16(float* c, const unsigned* a, const unsigned* b) {
    asm volatile(
        "mma.sync.aligned.m16n8k16.row.col.f32.bf16.bf16.f32 "
        "{%0,%1,%2,%3},{%4,%5,%6,%7},{%8,%9},{%0,%1,%2,%3};"
        : "+f"(c[0]), "+f"(c[1]), "+f"(c[2]), "+f"(c[3])
        : "r"(a[0]), "r"(a[1]), "r"(a[2]), "r"(a[3]), "r"(b[0]), "r"(b[1]));
}
__device__ __forceinline__ void store_hl(__nv_bfloat16* Ohi, __nv_bfloat16* Olo,
                                         long long off, float v0, float v1) {
    __nv_bfloat16 h0 = __float2bfloat16_rn(v0), h1 = __float2bfloat16_rn(v1);
    __nv_bfloat162 hp; hp.x = h0; hp.y = h1;
    *(__nv_bfloat162*)(Ohi + off) = hp;
    __nv_bfloat162 lp;
    lp.x = __float2bfloat16_rn(v0 - __bfloat162float(h0));
    lp.y = __float2bfloat16_rn(v1 - __bfloat162float(h1));
    *(__nv_bfloat162*)(Olo + off) = lp;
}

// 4-stage dynamic smem: per stage mats {Ahi, Alo, Whi, Wlo}, each 128 rows x 24 bf16
#define MAT_BYTES 6144u
#define NSTAGE 4
#define SMEM_BYTES (NSTAGE * 4 * MAT_BYTES)   // 98304

__device__ __forceinline__ void mma_chunk(unsigned mbase, int aoff0, int aoff1,
                                          const int* woff, float acc[2][8][4]) {
    unsigned ah[2][4], al[2][4];
    ldsm4(ah[0], mbase + 0 * MAT_BYTES + aoff0);
    ldsm4(ah[1], mbase + 0 * MAT_BYTES + aoff1);
    ldsm4(al[0], mbase + 1 * MAT_BYTES + aoff0);
    ldsm4(al[1], mbase + 1 * MAT_BYTES + aoff1);
#pragma unroll
    for (int ng = 0; ng < 4; ng++) {
        unsigned bh[4], bl[4];
        ldsm4(bh, mbase + 2 * MAT_BYTES + woff[ng]);
        ldsm4(bl, mbase + 3 * MAT_BYTES + woff[ng]);
#pragma unroll
        for (int mi = 0; mi < 2; mi++)
#pragma unroll
            for (int ns = 0; ns < 2; ns++) {
                float* C = acc[mi][ng * 2 + ns];
                mma_bf16(C, ah[mi], &bh[ns * 2]);
                mma_bf16(C, ah[mi], &bl[ns * 2]);
                mma_bf16(C, al[mi], &bh[ns * 2]);
            }
    }
}

// ---------------- layer GEMM: out = relu(A @ W + bias), K=128, BM=128 --------
__global__ void __launch_bounds__(256, 2)
mma_gemm_kernel(int a_sel, int w_idx, const float* __restrict__ bias, int o_sel) {
    extern __shared__ __nv_bfloat16 dynsm[];
    const unsigned base = (unsigned)__cvta_generic_to_shared(dynsm);

    const __nv_bfloat16 *Ahi, *Alo;
    sel_hl(a_sel, Ahi, Alo);
    __nv_bfloat16 *Ohi, *Olo;
    sel_out(o_sel, Ohi, Olo);
    const __nv_bfloat16* Whi = g_wthi[w_idx];
    const __nv_bfloat16* Wlo = g_wtlo[w_idx];

    const int tid = threadIdx.x, lane = tid & 31, w = tid >> 5;
    const int wm = w & 3, wn = w >> 2;
    const int rowBase = blockIdx.x * 128;
    const int g = lane >> 3, r = lane & 7;

    const int aoff0 = (wm * 32 + 0 + (g & 1) * 8 + r) * 48 + (g >> 1) * 16;
    const int aoff1 = (wm * 32 + 16 + (g & 1) * 8 + r) * 48 + (g >> 1) * 16;
    int woff[4];
#pragma unroll
    for (int ng = 0; ng < 4; ng++)
        woff[ng] = (wn * 64 + ng * 16 + (g >> 1) * 8 + r) * 48 + (g & 1) * 16;

    float acc[2][8][4];
#pragma unroll
    for (int i = 0; i < 2; i++)
#pragma unroll
        for (int j = 0; j < 8; j++)
#pragma unroll
            for (int q = 0; q < 4; q++) acc[i][j][q] = 0.f;

    const int crow = tid >> 1, chalf = tid & 1;
    const unsigned dsto = (unsigned)(crow * 48 + chalf * 16);
    const bool aok = (rowBase + crow) < N_NODES;
    const long long arow = (long long)(rowBase + crow) * 128;

#pragma unroll
    for (int pc = 0; pc < 3; pc++) {
        unsigned mb = base + (unsigned)pc * 4 * MAT_BYTES;
        int kb = pc * 16 + chalf * 8;
        cp16(mb + 0 * MAT_BYTES + dsto, Ahi + arow + kb, aok);
        cp16(mb + 1 * MAT_BYTES + dsto, Alo + arow + kb, aok);
        cp16(mb + 2 * MAT_BYTES + dsto, Whi + crow * 128 + kb, true);
        cp16(mb + 3 * MAT_BYTES + dsto, Wlo + crow * 128 + kb, true);
        cp_commit();
    }

#pragma unroll
    for (int c = 0; c < 8; c++) {
        if (c < 6) cp_wait<2>();
        else if (c == 6) cp_wait<1>();
        else cp_wait<0>();
        __syncthreads();
        mma_chunk(base + (unsigned)(c & 3) * 4 * MAT_BYTES, aoff0, aoff1, woff, acc);
        if (c + 3 < 8) {
            unsigned mb = base + (unsigned)((c + 3) & 3) * 4 * MAT_BYTES;
            int kb = (c + 3) * 16 + chalf * 8;
            cp16(mb + 0 * MAT_BYTES + dsto, Ahi + arow + kb, aok);
            cp16(mb + 1 * MAT_BYTES + dsto, Alo + arow + kb, aok);
            cp16(mb + 2 * MAT_BYTES + dsto, Whi + crow * 128 + kb, true);
            cp16(mb + 3 * MAT_BYTES + dsto, Wlo + crow * 128 + kb, true);
            cp_commit();
        }
    }

#pragma unroll
    for (int ni = 0; ni < 8; ni++) {
        int n0 = wn * 64 + ni * 8 + 2 * (lane & 3);
        float2 bv = *(const float2*)&bias[n0];
#pragma unroll
        for (int mi = 0; mi < 2; mi++) {
            int r0 = rowBase + wm * 32 + mi * 16 + (lane >> 2);
            float* C = acc[mi][ni];
            float v0 = fmaxf(C[0] + bv.x, 0.f), v1 = fmaxf(C[1] + bv.y, 0.f);
            float v2 = fmaxf(C[2] + bv.x, 0.f), v3 = fmaxf(C[3] + bv.y, 0.f);
            if (r0 < N_NODES) store_hl(Ohi, Olo, (long long)r0 * 128 + n0, v0, v1);
            if (r0 + 8 < N_NODES) store_hl(Ohi, Olo, (long long)(r0 + 8) * 128 + n0, v2, v3);
        }
    }
}

// ---------------- final GEMM: out = concat(x,h0,h1,h2) @ fw + fb, K=512 ------
__device__ __forceinline__ void final_src(int s, const __nv_bfloat16*& hi,
                                          const __nv_bfloat16*& lo) {
    switch (s) {
        case 0: hi = g_xhi; lo = g_xlo; break;
        case 1: hi = g_hhi[0]; lo = g_hlo[0]; break;
        case 2: hi = g_hhi[1]; lo = g_hlo[1]; break;
        default: hi = g_hhi[2]; lo = g_hlo[2]; break;
    }
}

__global__ void __launch_bounds__(256, 2)
final_gemm_kernel(const float* __restrict__ fb, float* __restrict__ out) {
    extern __shared__ __nv_bfloat16 dynsm[];
    const unsigned base = (unsigned)__cvta_generic_to_shared(dynsm);

    const int tid = threadIdx.x, lane = tid & 31, w = tid >> 5;
    const int wm = w & 3, wn = w >> 2;
    const int rowBase = blockIdx.x * 128;
    const int g = lane >> 3, r = lane & 7;

    const int aoff0 = (wm * 32 + 0 + (g & 1) * 8 + r) * 48 + (g >> 1) * 16;
    const int aoff1 = (wm * 32 + 16 + (g & 1) * 8 + r) * 48 + (g >> 1) * 16;
    int woff[4];
#pragma unroll
    for (int ng = 0; ng < 4; ng++)
        woff[ng] = (wn * 64 + ng * 16 + (g >> 1) * 8 + r) * 48 + (g & 1) * 16;

    float acc[2][8][4];
#pragma unroll
    for (int i = 0; i < 2; i++)
#pragma unroll
        for (int j = 0; j < 8; j++)
#pragma unroll
            for (int q = 0; q < 4; q++) acc[i][j][q] = 0.f;

    const int crow = tid >> 1, chalf = tid & 1;
    const unsigned dsto = (unsigned)(crow * 48 + chalf * 16);
    const bool aok = (rowBase + crow) < N_NODES;
    const long long arow = (long long)(rowBase + crow) * 128;

#pragma unroll
    for (int pc = 0; pc < 3; pc++) {
        const __nv_bfloat16 *shi, *slo;
        final_src(pc >> 3, shi, slo);
        unsigned mb = base + (unsigned)pc * 4 * MAT_BYTES;
        int ka = (pc & 7) * 16 + chalf * 8;
        int kw = pc * 16 + chalf * 8;
        cp16(mb + 0 * MAT_BYTES + dsto, shi + arow + ka, aok);
        cp16(mb + 1 * MAT_BYTES + dsto, slo + arow + ka, aok);
        cp16(mb + 2 * MAT_BYTES + dsto, g_fwthi + crow * 512 + kw, true);
        cp16(mb + 3 * MAT_BYTES + dsto, g_fwtlo + crow * 512 + kw, true);
        cp_commit();
    }

    for (int c = 0; c < 32; c++) {
        if (c < 30) cp_wait<2>();
        else if (c == 30) cp_wait<1>();
        else cp_wait<0>();
        __syncthreads();
        mma_chunk(base + (unsigned)(c & 3) * 4 * MAT_BYTES, aoff0, aoff1, woff, acc);
        if (c + 3 < 32) {
            int cn = c + 3;
            const __nv_bfloat16 *shi, *slo;
            final_src(cn >> 3, shi, slo);
            unsigned mb = base + (unsigned)(cn & 3) * 4 * MAT_BYTES;
            int ka = (cn & 7) * 16 + chalf * 8;
            int kw = cn * 16 + chalf * 8;
            cp16(mb + 0 * MAT_BYTES + dsto, shi + arow + ka, aok);
            cp16(mb + 1 * MAT_BYTES + dsto, slo + arow + ka, aok);
            cp16(mb + 2 * MAT_BYTES + dsto, g_fwthi + crow * 512 + kw, true);
            cp16(mb + 3 * MAT_BYTES + dsto, g_fwtlo + crow * 512 + kw, true);
            cp_commit();
        }
    }

#pragma unroll
    for (int ni = 0; ni < 8; ni++) {
        int n0 = wn * 64 + ni * 8 + 2 * (lane & 3);
        float2 bv = *(const float2*)&fb[n0];
#pragma unroll
        for (int mi = 0; mi < 2; mi++) {
            int r0 = rowBase + wm * 32 + mi * 16 + (lane >> 2);
            float* C = acc[mi][ni];
            if (r0 < N_NODES) {
                float2 o = make_float2(C[0] + bv.x, C[1] + bv.y);
                *(float2*)&out[(long long)r0 * 128 + n0] = o;
            }
            if (r0 + 8 < N_NODES) {
                float2 o = make_float2(C[2] + bv.x, C[3] + bv.y);
                *(float2*)&out[(long long)(r0 + 8) * 128 + n0] = o;
            }
        }
    }
}

// ---------------- launch ----------------
extern "C" void kernel_launch(void* const* d_in, const int* in_sizes, int n_in,
                              void* d_out, int out_size) {
    const float* x   = (const float*)d_in[0];
    const int*   ei  = (const int*)d_in[1];
    const float* W1  = (const float*)d_in[2];
    const float* b1  = (const float*)d_in[3];
    const float* W2  = (const float*)d_in[4];
    const float* b2  = (const float*)d_in[5];
    const float* eps = (const float*)d_in[6];
    const float* fw  = (const float*)d_in[7];
    const float* fb  = (const float*)d_in[8];
    float* out = (float*)d_out;

    cudaFuncSetAttribute(mma_gemm_kernel,
                         cudaFuncAttributeMaxDynamicSharedMemorySize, SMEM_BYTES);
    cudaFuncSetAttribute(final_gemm_kernel,
                         cudaFuncAttributeMaxDynamicSharedMemorySize, SMEM_BYTES);

    const int PB = (NELEM / 8 + 255) / 256;          // 3125 (covers all prep work)
    const int EB8 = (N_EDGES / 8 + 255) / 256;       // 313
    const int GB = (N_NODES + 127) / 128;            // 391
    const int AB = (N_NODES * 32 + 255) / 256;       // warp per node

    // fused prep + CSR build
    prep_kernel<<<PB, 256>>>(x, ei, W1, W2, fw);
    hist_kernel<<<EB8, 256>>>(ei);
    bsum_kernel<<<NBLK, 256>>>();
    rowptr_kernel<<<NBLK, 256>>>();
    scatter_kernel<<<EB8, 256>>>(ei);

    // 3 GIN layers
    int hin[3]  = { SEL_X, SEL_H0, SEL_H1 };
    int hout[3] = { SEL_H0, SEL_H1, SEL_H2 };
    for (int l = 0; l < 3; l++) {
        agg_kernel<<<AB, 256>>>(hin[l], eps, l);
        mma_gemm_kernel<<<GB, 256, SMEM_BYTES>>>(SEL_T, 2 * l,     b1 + l * 128, SEL_Z);
        mma_gemm_kernel<<<GB, 256, SMEM_BYTES>>>(SEL_Z, 2 * l + 1, b2 + l * 128, hout[l]);
    }
    final_gemm_kernel<<<GB, 256, SMEM_BYTES>>>(fb, out);
}